// round 1
// baseline (speedup 1.0000x reference)
#include <cuda_runtime.h>
#include <math.h>

// Problem constants
#define N_IMG  32
#define CI_TOT 64
#define HH     128
#define WW     128
#define CO_TOT 128
#define HO     126
#define WO     126

// Tiling
#define TILE_H 16
#define TILE_W 64
#define PX     4      // pixels per thread along W
#define TXN    16     // threads along W
#define TYN    16     // threads along H
#define CI_CH  16     // input-channel chunk in smem
#define CO_CH  8      // output-channel chunk (register accumulators)

#define XS_H   (TILE_H + 2)   // 18
#define XS_W   (TILE_W + 2)   // 66
#define XS_STR 66

#define SMEM_BYTES ((CI_CH * XS_H * XS_STR + CO_CH * CI_CH * 9) * 4)

__global__ __launch_bounds__(256, 2)
void conv_min_tanh_kernel(const float* __restrict__ x,
                          const float* __restrict__ w,
                          const float* __restrict__ bias,
                          float* __restrict__ out) {
    extern __shared__ float smem[];
    float* xs = smem;                                   // [CI_CH][XS_H][XS_STR]
    float* ws = smem + CI_CH * XS_H * XS_STR;           // [CO_CH][CI_CH][9]

    const int tx  = threadIdx.x;           // 0..15
    const int ty  = threadIdx.y;           // 0..15
    const int tid = ty * TXN + tx;
    const int gx0 = blockIdx.x * TILE_W;   // 0 or 64
    const int gy0 = blockIdx.y * TILE_H;   // 0..112
    const int n   = blockIdx.z;

    float m[PX];
#pragma unroll
    for (int p = 0; p < PX; p++) m[p] = INFINITY;

    const size_t x_img = (size_t)n * CI_TOT * HH * WW;

    for (int co0 = 0; co0 < CO_TOT; co0 += CO_CH) {
        float acc[CO_CH][PX];
#pragma unroll
        for (int co = 0; co < CO_CH; co++)
#pragma unroll
            for (int p = 0; p < PX; p++) acc[co][p] = 0.0f;

        for (int ci0 = 0; ci0 < CI_TOT; ci0 += CI_CH) {
            __syncthreads();   // protect previous tile users

            // ---- stage x tile: 16 ci x 18 rows x 66 cols ----
            for (int i = tid; i < CI_CH * XS_H * XS_W; i += TXN * TYN) {
                int ci = i / (XS_H * XS_W);
                int r  = (i / XS_W) % XS_H;
                int c  = i % XS_W;
                int gy = gy0 + r;
                int gx = gx0 + c;
                float v = 0.0f;
                if (gy < HH && gx < WW)
                    v = x[x_img + ((size_t)(ci0 + ci) * HH + gy) * WW + gx];
                xs[(ci * XS_H + r) * XS_STR + c] = v;
            }
            // ---- stage weights: 8 co x 16 ci x 9 ----
            for (int i = tid; i < CO_CH * CI_CH * 9; i += TXN * TYN) {
                int co  = i / (CI_CH * 9);
                int rem = i % (CI_CH * 9);
                int ci  = rem / 9;
                int t   = rem % 9;
                ws[i] = w[((size_t)(co0 + co) * CI_TOT + ci0 + ci) * 9 + t];
            }
            __syncthreads();

            // ---- compute: register-blocked 8co x 4px ----
#pragma unroll 1
            for (int ci = 0; ci < CI_CH; ci++) {
                float xr[3][PX + 2];
#pragma unroll
                for (int ky = 0; ky < 3; ky++)
#pragma unroll
                    for (int c = 0; c < PX + 2; c++)
                        xr[ky][c] = xs[(ci * XS_H + ty + ky) * XS_STR + tx * PX + c];

#pragma unroll
                for (int co = 0; co < CO_CH; co++) {
#pragma unroll
                    for (int ky = 0; ky < 3; ky++) {
#pragma unroll
                        for (int kx = 0; kx < 3; kx++) {
                            float wv = ws[(co * CI_CH + ci) * 9 + ky * 3 + kx];
#pragma unroll
                            for (int p = 0; p < PX; p++)
                                acc[co][p] = fmaf(xr[ky][kx + p], wv, acc[co][p]);
                        }
                    }
                }
            }
        }

        // ---- fold this co-chunk into the running min ----
#pragma unroll
        for (int co = 0; co < CO_CH; co++) {
            float b = __ldg(&bias[co0 + co]);
#pragma unroll
            for (int p = 0; p < PX; p++)
                m[p] = fminf(m[p], acc[co][p] + b);
        }
    }

    // ---- epilogue: tanh(tanh(min)) ----
    const int oy = gy0 + ty;
    if (oy < HO) {
#pragma unroll
        for (int p = 0; p < PX; p++) {
            int ox = gx0 + tx * PX + p;
            if (ox < WO)
                out[((size_t)n * HO + oy) * WO + ox] = tanhf(tanhf(m[p]));
        }
    }
}

extern "C" void kernel_launch(void* const* d_in, const int* in_sizes, int n_in,
                              void* d_out, int out_size) {
    const float* x    = (const float*)d_in[0];
    const float* w    = (const float*)d_in[1];
    const float* bias = (const float*)d_in[2];
    float* out        = (float*)d_out;

    cudaFuncSetAttribute(conv_min_tanh_kernel,
                         cudaFuncAttributeMaxDynamicSharedMemorySize, SMEM_BYTES);

    dim3 block(TXN, TYN);
    dim3 grid((WO + TILE_W - 1) / TILE_W,   // 2
              (HO + TILE_H - 1) / TILE_H,   // 8
              N_IMG);                        // 32
    conv_min_tanh_kernel<<<grid, block, SMEM_BYTES>>>(x, w, bias, out);
}

// round 2
// speedup vs baseline: 5.1641x; 5.1641x over previous
#include <cuda_runtime.h>
#include <math.h>

// Problem constants
#define N_IMG  32
#define CI_TOT 64
#define HH     128
#define WW     128
#define CO_TOT 128
#define HO     126
#define WO     126

// GEMM tiling: CTA = 128 pixels (8 y-rows x 16 x-cols) x 128 co, K = 576
#define TPX 16      // x-pixels per tile
#define TPY 8       // y-rows per tile (one per warp)
#define CI_CH 8     // input channels per k-chunk stage

// smem layouts (padded for conflict-free MMA fragment gathers)
#define XS_ROWS 10          // TPY + 2 halo
#define XS_COLS 18          // TPX + 2 halo
#define XS_STR  20          // pad: ci stride = 200 words -> ci*8 mod 32 banks
#define WS_STR  136         // pad: ci stride -> ci*8 mod 32 banks

// Transposed+tf32 weights: [tap(9)][ci(64)][co(128)]
__device__ unsigned g_wT[9 * 64 * 128];

__device__ __forceinline__ unsigned f2tf32(float v) {
    unsigned r;
    asm("cvt.rna.tf32.f32 %0, %1;" : "=r"(r) : "f"(v));
    return r;
}

__global__ void transpose_w_kernel(const float* __restrict__ w) {
    int i = blockIdx.x * 256 + threadIdx.x;
    if (i < 9 * 64 * 128) {
        int tap = i >> 13;          // /8192
        int ci  = (i >> 7) & 63;
        int co  = i & 127;
        g_wT[i] = f2tf32(w[(co * 64 + ci) * 9 + tap]);
    }
}

__device__ __forceinline__ void mma_tf32(float d[4], const unsigned a[4],
                                         unsigned b0, unsigned b1) {
    asm volatile(
        "mma.sync.aligned.m16n8k8.row.col.f32.tf32.tf32.f32 "
        "{%0,%1,%2,%3}, {%4,%5,%6,%7}, {%8,%9}, {%0,%1,%2,%3};\n"
        : "+f"(d[0]), "+f"(d[1]), "+f"(d[2]), "+f"(d[3])
        : "r"(a[0]), "r"(a[1]), "r"(a[2]), "r"(a[3]), "r"(b0), "r"(b1));
}

__global__ __launch_bounds__(256, 2)
void conv_mma_kernel(const float* __restrict__ x,
                     const float* __restrict__ bias,
                     float* __restrict__ out) {
    __shared__ unsigned xs[CI_CH * XS_ROWS * XS_STR];   // 1600 w = 6.4 KB
    __shared__ unsigned ws[9 * CI_CH * WS_STR];         // 9792 w = 39.2 KB
    __shared__ float    bs[CO_TOT];

    const int tid  = threadIdx.x;
    const int wid  = tid >> 5;      // 0..7 = y-row within tile
    const int lane = tid & 31;
    const int q    = lane & 3;      // threadID_in_group
    const int g    = lane >> 2;     // groupID

    const int x0 = blockIdx.x * TPX;
    const int y0 = blockIdx.y * TPY;
    const int n  = blockIdx.z;
    const size_t xbase = (size_t)n * CI_TOT * HH * WW;

    if (tid < CO_TOT) bs[tid] = bias[tid];

    float d[16][4];
#pragma unroll
    for (int t = 0; t < 16; t++)
#pragma unroll
        for (int j = 0; j < 4; j++) d[t][j] = 0.0f;

    // per-thread fragment address bases
    const int a_base = (q * XS_ROWS + wid) * XS_STR + g;   // a0 at +ky*20+kx
    const int w_base = q * WS_STR + g;                     // b0 at tap*1088 + 8t

    for (int ci0 = 0; ci0 < CI_TOT; ci0 += CI_CH) {
        __syncthreads();
        // ---- stage weights: [9 taps][8 ci][128 co] (coalesced from g_wT) ----
        for (int i = tid; i < 9 * CI_CH * 128; i += 256) {
            int tap = i >> 10;
            int ci  = (i >> 7) & 7;
            int co  = i & 127;
            ws[(tap * CI_CH + ci) * WS_STR + co] =
                g_wT[(tap * 64 + ci0 + ci) * 128 + co];
        }
        // ---- stage x tile: [8 ci][10 rows][18 cols], cvt to tf32 ----
        for (int i = tid; i < CI_CH * XS_ROWS * XS_COLS; i += 256) {
            int ci = i / (XS_ROWS * XS_COLS);
            int r  = (i / XS_COLS) % XS_ROWS;
            int c  = i % XS_COLS;
            int gy = y0 + r, gx = x0 + c;
            float v = 0.0f;
            if (gy < HH && gx < WW)
                v = x[xbase + ((size_t)(ci0 + ci) * HH + gy) * WW + gx];
            xs[(ci * XS_ROWS + r) * XS_STR + c] = f2tf32(v);
        }
        __syncthreads();

        // ---- 9 taps x 16 n-tiles of m16n8k8 ----
#pragma unroll
        for (int tap = 0; tap < 9; tap++) {
            const int ky = tap / 3, kx = tap % 3;
            const int ai = a_base + ky * XS_STR + kx;
            unsigned a[4];
            a[0] = xs[ai];                              // (row g,   k=q)
            a[1] = xs[ai + 8];                          // (row g+8, k=q)
            a[2] = xs[ai + 4 * XS_ROWS * XS_STR];       // (row g,   k=q+4)
            a[3] = xs[ai + 4 * XS_ROWS * XS_STR + 8];   // (row g+8, k=q+4)

            const int wi = tap * CI_CH * WS_STR + w_base;
#pragma unroll
            for (int t = 0; t < 16; t++) {
                unsigned b0 = ws[wi + 8 * t];                  // (k=q,   co=8t+g)
                unsigned b1 = ws[wi + 4 * WS_STR + 8 * t];     // (k=q+4, co=8t+g)
                mma_tf32(d[t], a, b0, b1);
            }
        }
    }

    // ---- epilogue: +bias, min over 128 co, tanh(tanh) ----
    float mlo = INFINITY, mhi = INFINITY;
#pragma unroll
    for (int t = 0; t < 16; t++) {
        float b0 = bs[8 * t + 2 * q];
        float b1 = bs[8 * t + 2 * q + 1];
        mlo = fminf(mlo, fminf(d[t][0] + b0, d[t][1] + b1));
        mhi = fminf(mhi, fminf(d[t][2] + b0, d[t][3] + b1));
    }
    // reduce across the 4 lanes of each group (co coverage union)
    mlo = fminf(mlo, __shfl_xor_sync(0xFFFFFFFFu, mlo, 1));
    mlo = fminf(mlo, __shfl_xor_sync(0xFFFFFFFFu, mlo, 2));
    mhi = fminf(mhi, __shfl_xor_sync(0xFFFFFFFFu, mhi, 1));
    mhi = fminf(mhi, __shfl_xor_sync(0xFFFFFFFFu, mhi, 2));

    if (q == 0) {
        const int yy = y0 + wid;
        if (yy < HO) {
            const int xlo = x0 + g, xhi = x0 + g + 8;
            if (xlo < WO)
                out[((size_t)n * HO + yy) * WO + xlo] = tanhf(tanhf(mlo));
            if (xhi < WO)
                out[((size_t)n * HO + yy) * WO + xhi] = tanhf(tanhf(mhi));
        }
    }
}

extern "C" void kernel_launch(void* const* d_in, const int* in_sizes, int n_in,
                              void* d_out, int out_size) {
    const float* x    = (const float*)d_in[0];
    const float* w    = (const float*)d_in[1];
    const float* bias = (const float*)d_in[2];
    float* out        = (float*)d_out;

    transpose_w_kernel<<<(9 * 64 * 128 + 255) / 256, 256>>>(w);

    dim3 grid((WO + TPX - 1) / TPX,   // 8
              (HO + TPY - 1) / TPY,   // 16
              N_IMG);                 // 32
    conv_mma_kernel<<<grid, 256>>>(x, bias, out);
}

// round 3
// speedup vs baseline: 10.3944x; 2.0128x over previous
#include <cuda_runtime.h>
#include <cuda_bf16.h>
#include <math.h>

// Problem constants
#define N_IMG  32
#define CI_TOT 64
#define HH     128
#define WW     128
#define CO_TOT 128
#define HO     126
#define WO     126

// CTA tile: 128 pixels (8 y-rows x 16 x-cols) x 128 co. 8 warps:
//   pg = wid>>1 (4 pixel groups, 2 y-rows each -> M=32/warp)
//   cg = wid&1  (2 co groups, 64 co each   -> N=64/warp)
#define TPX 16
#define TPY 8
#define CI2_CH 8    // ci-PAIRS per k-chunk (16 ci) -> 4 chunks

// smem layouts (strides chosen so q-planes land on distinct banks)
#define XS_ROWS 10          // TPY + 2 halo
#define XS_COLS 18          // TPX + 2 halo
#define XS_STR  20          // 10*? : q*200 mod 32 = q*8
#define WS_STR  136         // q*136 mod 32 = q*8

// Packed bf16x2 weights: [tap(9)][ci2(32)][co(128)], word = (bf16 ci even | bf16 ci odd<<16)
__device__ unsigned g_wT2[9 * 32 * 128];

__global__ void pack_w_kernel(const float* __restrict__ w) {
    int i = blockIdx.x * 256 + threadIdx.x;
    if (i < 9 * 32 * 128) {
        int tap = i >> 12;            // /4096
        int ci2 = (i >> 7) & 31;
        int co  = i & 127;
        float w0 = w[((size_t)co * 64 + 2 * ci2) * 9 + tap];
        float w1 = w[((size_t)co * 64 + 2 * ci2 + 1) * 9 + tap];
        __nv_bfloat162 p = __float22bfloat162_rn(make_float2(w0, w1));
        g_wT2[i] = *reinterpret_cast<unsigned*>(&p);
    }
}

__device__ __forceinline__ void mma_bf16(float d[4], const unsigned a[4],
                                         unsigned b0, unsigned b1) {
    asm volatile(
        "mma.sync.aligned.m16n8k16.row.col.f32.bf16.bf16.f32 "
        "{%0,%1,%2,%3}, {%4,%5,%6,%7}, {%8,%9}, {%0,%1,%2,%3};\n"
        : "+f"(d[0]), "+f"(d[1]), "+f"(d[2]), "+f"(d[3])
        : "r"(a[0]), "r"(a[1]), "r"(a[2]), "r"(a[3]), "r"(b0), "r"(b1));
}

__global__ __launch_bounds__(256, 2)
void conv_mma_bf16_kernel(const float* __restrict__ x,
                          const float* __restrict__ bias,
                          float* __restrict__ out) {
    __shared__ unsigned xs[CI2_CH * XS_ROWS * XS_STR];   // 1600 w
    __shared__ unsigned ws[9 * CI2_CH * WS_STR];         // 9792 w
    __shared__ float    bs[CO_TOT];                      // 128
    __shared__ float    red[2][TPY][TPX];                // 256

    const int tid  = threadIdx.x;
    const int wid  = tid >> 5;
    const int lane = tid & 31;
    const int q    = lane & 3;
    const int g    = lane >> 2;
    const int pg   = wid >> 1;      // pixel group: y rows 2pg, 2pg+1
    const int cg   = wid & 1;       // co group: cg*64 .. +63
    const int nb   = cg * 64;

    const int x0 = blockIdx.x * TPX;
    const int y0 = blockIdx.y * TPY;
    const int n  = blockIdx.z;
    const size_t xbase = (size_t)n * CI_TOT * HH * WW;

    if (tid < CO_TOT) bs[tid] = bias[tid];

    float d[2][8][4];   // [m-tile][n-tile][frag]
#pragma unroll
    for (int m = 0; m < 2; m++)
#pragma unroll
        for (int t = 0; t < 8; t++)
#pragma unroll
            for (int j = 0; j < 4; j++) d[m][t][j] = 0.0f;

    for (int chunk = 0; chunk < 4; chunk++) {
        __syncthreads();
        const int ci2_0 = chunk * CI2_CH;

        // ---- stage weights: [9 tap][8 ci2][128 co] ----
        for (int i = tid; i < 9 * CI2_CH * 128; i += 256) {
            int tap = i >> 10;
            int c2  = (i >> 7) & 7;
            int co  = i & 127;
            ws[(tap * CI2_CH + c2) * WS_STR + co] =
                g_wT2[((size_t)tap * 32 + ci2_0 + c2) * 128 + co];
        }
        // ---- stage x tile: [8 ci2][10 rows][18 cols], packed bf16x2 ----
        for (int i = tid; i < CI2_CH * XS_ROWS * XS_COLS; i += 256) {
            int c2 = i / (XS_ROWS * XS_COLS);
            int r  = (i / XS_COLS) % XS_ROWS;
            int c  = i % XS_COLS;
            int gy = y0 + r, gx = x0 + c;
            float v0 = 0.0f, v1 = 0.0f;
            if (gy < HH && gx < WW) {
                size_t base = xbase + ((size_t)(2 * (ci2_0 + c2)) * HH + gy) * WW + gx;
                v0 = x[base];
                v1 = x[base + (size_t)HH * WW];
            }
            __nv_bfloat162 p = __float22bfloat162_rn(make_float2(v0, v1));
            xs[(c2 * XS_ROWS + r) * XS_STR + c] = *reinterpret_cast<unsigned*>(&p);
        }
        __syncthreads();

        // ---- 9 taps x (2 m-tiles x 8 n-tiles) of m16n8k16 ----
#pragma unroll
        for (int tap = 0; tap < 9; tap++) {
            const int ky = tap / 3, kx = tap % 3;
            unsigned a[2][4];
#pragma unroll
            for (int m = 0; m < 2; m++) {
                const int ai = (q * XS_ROWS + (pg * 2 + m + ky)) * XS_STR + kx + g;
                a[m][0] = xs[ai];                               // (x=g,   k=2q,2q+1)
                a[m][1] = xs[ai + 8];                           // (x=g+8, k=2q..)
                a[m][2] = xs[ai + 4 * XS_ROWS * XS_STR];        // (x=g,   k=2q+8..)
                a[m][3] = xs[ai + 4 * XS_ROWS * XS_STR + 8];    // (x=g+8, k=2q+8..)
            }
            const int wi = tap * CI2_CH * WS_STR + q * WS_STR + nb + g;
#pragma unroll
            for (int t = 0; t < 8; t++) {
                unsigned b0 = ws[wi + 8 * t];                   // (k=2q..,   co)
                unsigned b1 = ws[wi + 4 * WS_STR + 8 * t];      // (k=2q+8.., co)
                mma_bf16(d[0][t], a[0], b0, b1);
                mma_bf16(d[1][t], a[1], b0, b1);
            }
        }
    }

    // ---- epilogue: +bias, min over this warp's 64 co ----
#pragma unroll
    for (int m = 0; m < 2; m++) {
        float mlo = INFINITY, mhi = INFINITY;
#pragma unroll
        for (int t = 0; t < 8; t++) {
            float b0 = bs[nb + 8 * t + 2 * q];
            float b1 = bs[nb + 8 * t + 2 * q + 1];
            mlo = fminf(mlo, fminf(d[m][t][0] + b0, d[m][t][1] + b1));
            mhi = fminf(mhi, fminf(d[m][t][2] + b0, d[m][t][3] + b1));
        }
        // reduce over q (lane bits 0,1)
        mlo = fminf(mlo, __shfl_xor_sync(0xFFFFFFFFu, mlo, 1));
        mlo = fminf(mlo, __shfl_xor_sync(0xFFFFFFFFu, mlo, 2));
        mhi = fminf(mhi, __shfl_xor_sync(0xFFFFFFFFu, mhi, 1));
        mhi = fminf(mhi, __shfl_xor_sync(0xFFFFFFFFu, mhi, 2));
        if (q == 0) {
            red[cg][pg * 2 + m][g]     = mlo;
            red[cg][pg * 2 + m][g + 8] = mhi;
        }
    }
    __syncthreads();

    // ---- combine co-groups, tanh(tanh), store ----
    if (tid < TPY * TPX) {
        int yl = tid >> 4, xl = tid & 15;
        int yy = y0 + yl, xx = x0 + xl;
        if (yy < HO && xx < WO) {
            float v = fminf(red[0][yl][xl], red[1][yl][xl]);
            out[((size_t)n * HO + yy) * WO + xx] = tanhf(tanhf(v));
        }
    }
}

extern "C" void kernel_launch(void* const* d_in, const int* in_sizes, int n_in,
                              void* d_out, int out_size) {
    const float* x    = (const float*)d_in[0];
    const float* w    = (const float*)d_in[1];
    const float* bias = (const float*)d_in[2];
    float* out        = (float*)d_out;

    pack_w_kernel<<<(9 * 32 * 128 + 255) / 256, 256>>>(w);

    dim3 grid((WO + TPX - 1) / TPX,   // 8
              (HO + TPY - 1) / TPY,   // 16
              N_IMG);                 // 32
    conv_mma_bf16_kernel<<<grid, 256>>>(x, bias, out);
}

// round 4
// speedup vs baseline: 14.9534x; 1.4386x over previous
#include <cuda_runtime.h>
#include <cuda_bf16.h>
#include <math.h>

// Problem constants
#define N_IMG  32
#define CI_TOT 64
#define HH     128
#define WW     128
#define CO_TOT 128
#define HO     126
#define WO     126

#define TPX 16
#define TPY 8

// ---- packed operand scratch (device globals; no allocation) ----
// g_xP: bf16x2 pairs along ci: [n(32)][ci2(32)][h(128)][w(128)]
__device__ unsigned g_xP[32u * 32u * 128u * 128u];
// g_wP: bf16x2: [tap(9)][co(128)][ci2(32)]
__device__ unsigned g_wP[9 * 128 * 32];

__global__ void pack_x_kernel(const float* __restrict__ x) {
    unsigned i = blockIdx.x * 256 + threadIdx.x;   // 16777216 total
    unsigned wq  = i & 127;
    unsigned h   = (i >> 7) & 127;
    unsigned ci2 = (i >> 14) & 31;
    unsigned n   = i >> 19;
    size_t s = ((size_t)(n * 64 + 2 * ci2) * 128 + h) * 128 + wq;
    float v0 = x[s];
    float v1 = x[s + 128 * 128];
    __nv_bfloat162 p = __float22bfloat162_rn(make_float2(v0, v1));
    g_xP[i] = *reinterpret_cast<unsigned*>(&p);
}

__global__ void pack_w_kernel(const float* __restrict__ w) {
    int i = blockIdx.x * 256 + threadIdx.x;
    if (i < 9 * 128 * 32) {
        int ci2 = i & 31;
        int co  = (i >> 5) & 127;
        int tap = i >> 12;
        float w0 = w[((size_t)co * 64 + 2 * ci2) * 9 + tap];
        float w1 = w[((size_t)co * 64 + 2 * ci2 + 1) * 9 + tap];
        __nv_bfloat162 p = __float22bfloat162_rn(make_float2(w0, w1));
        g_wP[i] = *reinterpret_cast<unsigned*>(&p);
    }
}

// ---- smem layout (bytes), double buffered ----
// xs buf: [10 rows][18 cols] x 12 words (8 data + 4 pad) = 8640 B
// ws buf: [9 taps][128 co x 2 units x 16B swizzled] = 36864 B
#define SMEM_XS0 0
#define SMEM_XS1 8640
#define SMEM_WS0 17280
#define SMEM_WS1 54144
#define SMEM_BS  91008
#define SMEM_RED 91520
#define SMEM_TOTAL 92544

__device__ __forceinline__ void ldsm4(unsigned r[4], unsigned addr) {
    asm volatile("ldmatrix.sync.aligned.m8n8.x4.shared.b16 {%0,%1,%2,%3}, [%4];"
                 : "=r"(r[0]), "=r"(r[1]), "=r"(r[2]), "=r"(r[3]) : "r"(addr));
}
__device__ __forceinline__ void cp4(unsigned dst, const void* src, unsigned sz) {
    asm volatile("cp.async.ca.shared.global [%0], [%1], 4, %2;"
                 :: "r"(dst), "l"(src), "r"(sz));
}
__device__ __forceinline__ void cp16(unsigned dst, const void* src) {
    asm volatile("cp.async.cg.shared.global [%0], [%1], 16;"
                 :: "r"(dst), "l"(src));
}
__device__ __forceinline__ void mma_bf16(float d[4], const unsigned a[4],
                                         unsigned b0, unsigned b1) {
    asm volatile(
        "mma.sync.aligned.m16n8k16.row.col.f32.bf16.bf16.f32 "
        "{%0,%1,%2,%3}, {%4,%5,%6,%7}, {%8,%9}, {%0,%1,%2,%3};\n"
        : "+f"(d[0]), "+f"(d[1]), "+f"(d[2]), "+f"(d[3])
        : "r"(a[0]), "r"(a[1]), "r"(a[2]), "r"(a[3]), "r"(b0), "r"(b1));
}

__global__ __launch_bounds__(256, 2)
void conv_mma_kernel(const float* __restrict__ bias, float* __restrict__ out) {
    extern __shared__ unsigned char sm[];
    const unsigned smb = (unsigned)__cvta_generic_to_shared(sm);

    const int tid  = threadIdx.x;
    const int wid  = tid >> 5;
    const int lane = tid & 31;
    const int q    = lane & 3;
    const int g    = lane >> 2;
    const int pg   = wid >> 1;      // pixel group: y rows 2pg, 2pg+1
    const int cg   = wid & 1;       // co group: cg*64..+63
    const int nb   = cg * 64;

    const int x0 = blockIdx.x * TPX;
    const int y0 = blockIdx.y * TPY;
    const int n  = blockIdx.z;

    float* bs  = (float*)(sm + SMEM_BS);
    float* red = (float*)(sm + SMEM_RED);   // [2][8][16]

    if (tid < CO_TOT) bs[tid] = bias[tid];

    // per-lane ldmatrix offsets
    const unsigned axoff = (unsigned)((lane & 15) * 48 + (lane >> 4) * 16);
    unsigned boff[4];
    {
        int co_off = (lane & 7) | ((lane >> 4) << 3);
        int h      = (lane >> 3) & 1;
#pragma unroll
        for (int t = 0; t < 4; t++) {
            unsigned u = (unsigned)((nb + 16 * t + co_off) * 2 + h);
            u ^= (u >> 3) & 1;
            boff[t] = u * 16;
        }
    }

    float d[2][8][4];
#pragma unroll
    for (int m = 0; m < 2; m++)
#pragma unroll
        for (int t = 0; t < 8; t++)
#pragma unroll
            for (int j = 0; j < 4; j++) d[m][t][j] = 0.0f;

    // ---- prefetch helper ----
    auto prefetch = [&](int chunk, int pbuf) {
        unsigned xb = smb + (pbuf ? SMEM_XS1 : SMEM_XS0);
        unsigned wb = smb + (pbuf ? SMEM_WS1 : SMEM_WS0);
        // xs: [ci2(8)][r(10)][c(18)] -> dst [(r*18+c)*12 + ci2]
        for (int i = tid; i < 1440; i += 256) {
            int ci2 = i / 180;
            int rem = i % 180;
            int r = rem / 18, c = rem % 18;
            int gy = y0 + r, gx = x0 + c;
            unsigned dst = xb + (unsigned)(((r * 18 + c) * 12 + ci2) << 2);
            int gyc = gy < 127 ? gy : 127;
            int gxc = gx < 127 ? gx : 127;
            const unsigned* src =
                &g_xP[(((size_t)n * 32 + chunk * 8 + ci2) * 128 + gyc) * 128 + gxc];
            unsigned sz = (gy < HH && gx < WW) ? 4u : 0u;
            cp4(dst, src, sz);
        }
        // ws: 9 taps x 128 co x 2 16B-units, swizzled
        for (int i = tid; i < 2304; i += 256) {
            int tap = i >> 8;
            int co  = (i >> 1) & 127;
            int h   = i & 1;
            unsigned u = (unsigned)(co * 2 + h);
            u ^= (u >> 3) & 1;
            unsigned dst = wb + (unsigned)(tap * 4096) + u * 16;
            const unsigned* src = &g_wP[(tap * 128 + co) * 32 + chunk * 8 + h * 4];
            cp16(dst, src);
        }
        asm volatile("cp.async.commit_group;" ::: "memory");
    };

    prefetch(0, 0);

    for (int c = 0; c < 4; c++) {
        asm volatile("cp.async.wait_group 0;" ::: "memory");
        __syncthreads();
        if (c < 3) prefetch(c + 1, (c + 1) & 1);

        unsigned xb = smb + ((c & 1) ? SMEM_XS1 : SMEM_XS0);
        unsigned wb = smb + ((c & 1) ? SMEM_WS1 : SMEM_WS0);
        const unsigned arow = (unsigned)(2 * pg) * 864;   // pg*2 rows * 18 cols * 48B

#pragma unroll
        for (int tap = 0; tap < 9; tap++) {
            const int ky = tap / 3, kx = tap % 3;
            unsigned a0[4], a1[4];
            ldsm4(a0, xb + arow + (unsigned)((ky * 18 + kx) * 48) + axoff);
            ldsm4(a1, xb + arow + (unsigned)(((ky + 1) * 18 + kx) * 48) + axoff);
#pragma unroll
            for (int t = 0; t < 4; t++) {
                unsigned b[4];
                ldsm4(b, wb + (unsigned)(tap * 4096) + boff[t]);
                mma_bf16(d[0][2 * t],     a0, b[0], b[1]);
                mma_bf16(d[0][2 * t + 1], a0, b[2], b[3]);
                mma_bf16(d[1][2 * t],     a1, b[0], b[1]);
                mma_bf16(d[1][2 * t + 1], a1, b[2], b[3]);
            }
        }
    }

    // ---- epilogue: +bias, min over this warp's 64 co ----
#pragma unroll
    for (int m = 0; m < 2; m++) {
        float mlo = INFINITY, mhi = INFINITY;
#pragma unroll
        for (int t = 0; t < 8; t++) {
            float b0 = bs[nb + 8 * t + 2 * q];
            float b1 = bs[nb + 8 * t + 2 * q + 1];
            mlo = fminf(mlo, fminf(d[m][t][0] + b0, d[m][t][1] + b1));
            mhi = fminf(mhi, fminf(d[m][t][2] + b0, d[m][t][3] + b1));
        }
        mlo = fminf(mlo, __shfl_xor_sync(0xFFFFFFFFu, mlo, 1));
        mlo = fminf(mlo, __shfl_xor_sync(0xFFFFFFFFu, mlo, 2));
        mhi = fminf(mhi, __shfl_xor_sync(0xFFFFFFFFu, mhi, 1));
        mhi = fminf(mhi, __shfl_xor_sync(0xFFFFFFFFu, mhi, 2));
        if (q == 0) {
            red[(cg * 8 + pg * 2 + m) * 16 + g]     = mlo;
            red[(cg * 8 + pg * 2 + m) * 16 + g + 8] = mhi;
        }
    }
    __syncthreads();

    // ---- combine co-groups, tanh(tanh), store ----
    if (tid < TPY * TPX) {
        int yl = tid >> 4, xl = tid & 15;
        int yy = y0 + yl, xx = x0 + xl;
        if (yy < HO && xx < WO) {
            float v = fminf(red[yl * 16 + xl], red[(8 + yl) * 16 + xl]);
            out[((size_t)n * HO + yy) * WO + xx] = tanhf(tanhf(v));
        }
    }
}

extern "C" void kernel_launch(void* const* d_in, const int* in_sizes, int n_in,
                              void* d_out, int out_size) {
    const float* x    = (const float*)d_in[0];
    const float* w    = (const float*)d_in[1];
    const float* bias = (const float*)d_in[2];
    float* out        = (float*)d_out;

    pack_x_kernel<<<32u * 32u * 128u * 128u / 256u, 256>>>(x);
    pack_w_kernel<<<(9 * 128 * 32 + 255) / 256, 256>>>(w);

    cudaFuncSetAttribute(conv_mma_kernel,
                         cudaFuncAttributeMaxDynamicSharedMemorySize, SMEM_TOTAL);

    dim3 grid((WO + TPX - 1) / TPX,   // 8
              (HO + TPY - 1) / TPY,   // 16
              N_IMG);                 // 32
    conv_mma_kernel<<<grid, 256, SMEM_TOTAL>>>(bias, out);
}

// round 5
// speedup vs baseline: 17.3335x; 1.1592x over previous
#include <cuda_runtime.h>
#include <cuda_bf16.h>
#include <math.h>

// Problem constants
#define N_IMG  32
#define CI_TOT 64
#define HH     128
#define WW     128
#define CO_TOT 128
#define HO     126
#define WO     126

#define TPX 16
#define TPY 8

// ---- packed operand scratch (device globals; no allocation) ----
// g_xP2: bf16x2, [n(32)][chunk(4)][h(128)][w(128)][ci2-in-chunk(8)]  (32B per site)
__device__ unsigned g_xP2[32u * 4u * 128u * 128u * 8u];
// g_wP: bf16x2: [tap(9)][co(128)][ci2(32)]
__device__ unsigned g_wP[9 * 128 * 32];

__global__ void pack_x_kernel(const float* __restrict__ x) {
    unsigned i = blockIdx.x * 256 + threadIdx.x;   // 2,097,152 threads
    unsigned w     = i & 127;
    unsigned h     = (i >> 7) & 127;
    unsigned chunk = (i >> 14) & 3;
    unsigned n     = i >> 16;
    const float* src = x + (((size_t)(n * 64 + chunk * 16)) * 128 + h) * 128 + w;
    unsigned o[8];
#pragma unroll
    for (int c2 = 0; c2 < 8; c2++) {
        float v0 = src[(size_t)(2 * c2) * 16384];
        float v1 = src[(size_t)(2 * c2 + 1) * 16384];
        __nv_bfloat162 p = __float22bfloat162_rn(make_float2(v0, v1));
        o[c2] = *reinterpret_cast<unsigned*>(&p);
    }
    uint4* dst = reinterpret_cast<uint4*>(&g_xP2[(size_t)i * 8]);
    dst[0] = make_uint4(o[0], o[1], o[2], o[3]);
    dst[1] = make_uint4(o[4], o[5], o[6], o[7]);
}

__global__ void pack_w_kernel(const float* __restrict__ w) {
    int i = blockIdx.x * 256 + threadIdx.x;
    if (i < 9 * 128 * 32) {
        int ci2 = i & 31;
        int co  = (i >> 5) & 127;
        int tap = i >> 12;
        float w0 = w[((size_t)co * 64 + 2 * ci2) * 9 + tap];
        float w1 = w[((size_t)co * 64 + 2 * ci2 + 1) * 9 + tap];
        __nv_bfloat162 p = __float22bfloat162_rn(make_float2(w0, w1));
        g_wP[i] = *reinterpret_cast<unsigned*>(&p);
    }
}

// ---- smem layout (bytes), double buffered ----
#define SMEM_XS0 0
#define SMEM_XS1 8640
#define SMEM_WS0 17280
#define SMEM_WS1 54144
#define SMEM_BS  91008
#define SMEM_RED 91520
#define SMEM_TOTAL 92544

__device__ __forceinline__ void ldsm4(unsigned r[4], unsigned addr) {
    asm volatile("ldmatrix.sync.aligned.m8n8.x4.shared.b16 {%0,%1,%2,%3}, [%4];"
                 : "=r"(r[0]), "=r"(r[1]), "=r"(r[2]), "=r"(r[3]) : "r"(addr));
}
__device__ __forceinline__ void cp16z(unsigned dst, const void* src, unsigned sz) {
    asm volatile("cp.async.cg.shared.global [%0], [%1], 16, %2;"
                 :: "r"(dst), "l"(src), "r"(sz));
}
__device__ __forceinline__ void cp16(unsigned dst, const void* src) {
    asm volatile("cp.async.cg.shared.global [%0], [%1], 16;"
                 :: "r"(dst), "l"(src));
}
__device__ __forceinline__ void mma_bf16(float d[4], const unsigned a[4],
                                         unsigned b0, unsigned b1) {
    asm volatile(
        "mma.sync.aligned.m16n8k16.row.col.f32.bf16.bf16.f32 "
        "{%0,%1,%2,%3}, {%4,%5,%6,%7}, {%8,%9}, {%0,%1,%2,%3};\n"
        : "+f"(d[0]), "+f"(d[1]), "+f"(d[2]), "+f"(d[3])
        : "r"(a[0]), "r"(a[1]), "r"(a[2]), "r"(a[3]), "r"(b0), "r"(b1));
}

__global__ __launch_bounds__(256, 2)
void conv_mma_kernel(const float* __restrict__ bias, float* __restrict__ out) {
    extern __shared__ unsigned char sm[];
    const unsigned smb = (unsigned)__cvta_generic_to_shared(sm);

    const int tid  = threadIdx.x;
    const int wid  = tid >> 5;
    const int lane = tid & 31;
    const int q    = lane & 3;
    const int g    = lane >> 2;
    const int pg   = wid >> 1;
    const int cg   = wid & 1;
    const int nb   = cg * 64;

    const int x0 = blockIdx.x * TPX;
    const int y0 = blockIdx.y * TPY;
    const int n  = blockIdx.z;

    float* bs  = (float*)(sm + SMEM_BS);
    float* red = (float*)(sm + SMEM_RED);

    if (tid < CO_TOT) bs[tid] = bias[tid];

    const unsigned axoff = (unsigned)((lane & 15) * 48 + (lane >> 4) * 16);
    unsigned boff[4];
    {
        int co_off = (lane & 7) | ((lane >> 4) << 3);
        int h      = (lane >> 3) & 1;
#pragma unroll
        for (int t = 0; t < 4; t++) {
            unsigned u = (unsigned)((nb + 16 * t + co_off) * 2 + h);
            u ^= (u >> 3) & 1;
            boff[t] = u * 16;
        }
    }

    float d[2][8][4];
#pragma unroll
    for (int m = 0; m < 2; m++)
#pragma unroll
        for (int t = 0; t < 8; t++)
#pragma unroll
            for (int j = 0; j < 4; j++) d[m][t][j] = 0.0f;

    // ---- prefetch helper: 360 + 576 cp.async(16B) ----
    auto prefetch = [&](int chunk, int pbuf) {
        unsigned xb = smb + (pbuf ? SMEM_XS1 : SMEM_XS0);
        unsigned wb = smb + (pbuf ? SMEM_WS1 : SMEM_WS0);
        // xs: 180 sites (r,c), 32B each = 2 cp16; dst stride 48B/site
        for (int i = tid; i < 360; i += 256) {
            int site = i >> 1, half = i & 1;
            int r = site / 18, c = site % 18;
            int gy = y0 + r, gx = x0 + c;
            unsigned dst = xb + (unsigned)(site * 48 + half * 16);
            int gyc = gy < 127 ? gy : 127;
            int gxc = gx < 127 ? gx : 127;
            const unsigned* src =
                &g_xP2[((((size_t)n * 4 + chunk) * 128 + gyc) * 128 + gxc) * 8 + half * 4];
            unsigned sz = (gy < HH && gx < WW) ? 16u : 0u;
            cp16z(dst, src, sz);
        }
        // ws: 9 taps x 128 co x 2 16B-units, swizzled
        for (int i = tid; i < 2304; i += 256) {
            int tap = i >> 8;
            int co  = (i >> 1) & 127;
            int h   = i & 1;
            unsigned u = (unsigned)(co * 2 + h);
            u ^= (u >> 3) & 1;
            unsigned dst = wb + (unsigned)(tap * 4096) + u * 16;
            const unsigned* src = &g_wP[(tap * 128 + co) * 32 + chunk * 8 + h * 4];
            cp16(dst, src);
        }
        asm volatile("cp.async.commit_group;" ::: "memory");
    };

    prefetch(0, 0);

    for (int c = 0; c < 4; c++) {
        asm volatile("cp.async.wait_group 0;" ::: "memory");
        __syncthreads();
        if (c < 3) prefetch(c + 1, (c + 1) & 1);

        unsigned xb = smb + ((c & 1) ? SMEM_XS1 : SMEM_XS0);
        unsigned wb = smb + ((c & 1) ? SMEM_WS1 : SMEM_WS0);
        const unsigned arow = (unsigned)(2 * pg) * 864;

#pragma unroll
        for (int tap = 0; tap < 9; tap++) {
            const int ky = tap / 3, kx = tap % 3;
            unsigned a0[4], a1[4];
            ldsm4(a0, xb + arow + (unsigned)((ky * 18 + kx) * 48) + axoff);
            ldsm4(a1, xb + arow + (unsigned)(((ky + 1) * 18 + kx) * 48) + axoff);
#pragma unroll
            for (int t = 0; t < 4; t++) {
                unsigned b[4];
                ldsm4(b, wb + (unsigned)(tap * 4096) + boff[t]);
                mma_bf16(d[0][2 * t],     a0, b[0], b[1]);
                mma_bf16(d[0][2 * t + 1], a0, b[2], b[3]);
                mma_bf16(d[1][2 * t],     a1, b[0], b[1]);
                mma_bf16(d[1][2 * t + 1], a1, b[2], b[3]);
            }
        }
    }

    // ---- epilogue: +bias, min over this warp's 64 co ----
#pragma unroll
    for (int m = 0; m < 2; m++) {
        float mlo = INFINITY, mhi = INFINITY;
#pragma unroll
        for (int t = 0; t < 8; t++) {
            float b0 = bs[nb + 8 * t + 2 * q];
            float b1 = bs[nb + 8 * t + 2 * q + 1];
            mlo = fminf(mlo, fminf(d[m][t][0] + b0, d[m][t][1] + b1));
            mhi = fminf(mhi, fminf(d[m][t][2] + b0, d[m][t][3] + b1));
        }
        mlo = fminf(mlo, __shfl_xor_sync(0xFFFFFFFFu, mlo, 1));
        mlo = fminf(mlo, __shfl_xor_sync(0xFFFFFFFFu, mlo, 2));
        mhi = fminf(mhi, __shfl_xor_sync(0xFFFFFFFFu, mhi, 1));
        mhi = fminf(mhi, __shfl_xor_sync(0xFFFFFFFFu, mhi, 2));
        if (q == 0) {
            red[(cg * 8 + pg * 2 + m) * 16 + g]     = mlo;
            red[(cg * 8 + pg * 2 + m) * 16 + g + 8] = mhi;
        }
    }
    __syncthreads();

    if (tid < TPY * TPX) {
        int yl = tid >> 4, xl = tid & 15;
        int yy = y0 + yl, xx = x0 + xl;
        if (yy < HO && xx < WO) {
            float v = fminf(red[yl * 16 + xl], red[(8 + yl) * 16 + xl]);
            out[((size_t)n * HO + yy) * WO + xx] = tanhf(tanhf(v));
        }
    }
}

extern "C" void kernel_launch(void* const* d_in, const int* in_sizes, int n_in,
                              void* d_out, int out_size) {
    const float* x    = (const float*)d_in[0];
    const float* w    = (const float*)d_in[1];
    const float* bias = (const float*)d_in[2];
    float* out        = (float*)d_out;

    pack_x_kernel<<<(32u * 4u * 128u * 128u) / 256u, 256>>>(x);
    pack_w_kernel<<<(9 * 128 * 32 + 255) / 256, 256>>>(w);

    cudaFuncSetAttribute(conv_mma_kernel,
                         cudaFuncAttributeMaxDynamicSharedMemorySize, SMEM_TOTAL);

    dim3 grid((WO + TPX - 1) / TPX,   // 8
              (HO + TPY - 1) / TPY,   // 16
              N_IMG);                 // 32
    conv_mma_kernel<<<grid, 256, SMEM_TOTAL>>>(bias, out);
}